// round 4
// baseline (speedup 1.0000x reference)
#include <cuda_runtime.h>
#include <cuda_bf16.h>
#include <math.h>

// ---------------- problem constants ----------------
#define STEPS 20000
#define NCOL  2048
#define CH    250            // steps per chunk
#define NCH   (STEPS/CH)     // 80 chunks
#define NBINS 200000
#define HISTN (NBINS + 1)

// Rate matrix row sums (float64 -> float32 cast, replicating numpy exactly)
#define R1_SUM_D 123020000.0
__device__ __constant__ float c_rate[4] = {
    1.0e6f, (float)R1_SUM_D, 1.0e5f, (float)0.2
};

// thresholds: cumsum of row1 / S in float64, then float cast (numpy order)
__device__ __forceinline__ void get_thresholds(float& A, float& B, float& C) {
    const double c0 = 50000000.0 / R1_SUM_D;
    const double c2 = c0 + 3000000.0 / R1_SUM_D;
    const double c3 = c2 + 20000.0 / R1_SUM_D;
    A = (float)c0; B = (float)c2; C = (float)c3;
}

// reciprocal rates (only used for chunk offset estimation; final pass uses true div)
__device__ __constant__ float c_invr[4] = {
    1.0f / 1.0e6f, (float)(1.0 / R1_SUM_D), 1.0f / 1.0e5f, (float)(1.0 / 0.2)
};

// ---------------- device scratch (no allocations allowed) ----------------
__device__ unsigned      g_maps[NCH * NCOL];   // byte0: end(entry0), byte1: end(entry1), byte2: end(entry2/3)
__device__ float         g_dA[NCH * NCOL];     // chunk dwell total, entry state 0
__device__ float         g_dB[NCH * NCOL];     // entry state 1
__device__ float         g_dC[NCH * NCOL];     // entry state 2
__device__ float         g_dD[NCH * NCOL];     // entry state 3
__device__ unsigned char g_entry[NCH * NCOL];  // resolved entry state per chunk
__device__ float         g_offs[NCH * NCOL];   // resolved time offset per chunk
__device__ int           g_hist[HISTN];        // int histogram scratch

// f1: next state from state 1, given u_cat
__device__ __forceinline__ int f1_of(float u, float A, float B, float C) {
    return (u < A) ? 0 : ((u < B) ? 2 : ((u < C) ? 3 : 0));
}
__device__ __forceinline__ int advance(int s, int f1) {
    return (s == 0) ? 1 : ((s == 1) ? f1 : 0);
}
__device__ __forceinline__ float invr_of(int s) {
    return (s == 0) ? c_invr[0] : ((s == 1) ? c_invr[1] : ((s == 2) ? c_invr[2] : c_invr[3]));
}

// ---------------- K0: zero histogram ----------------
__global__ void k_zero() {
    int i = blockIdx.x * blockDim.x + threadIdx.x;
    if (i < HISTN) g_hist[i] = 0;
}

// ---------------- K1: per-chunk transfer maps + dwell totals ----------------
// Three REAL tracked trajectories (the noise is time-indexed, so no delay trick):
//   trajA: entry state 0, transitions driven by u[0..249]
//   trajB: entry state 1, transitions driven by u[0..249]
//   trajC: state 0 at time 1 (entry 2/3 both land in state 0 after step 0),
//          transitions driven by u[1..249]; tail dwell aT covers steps 1..249.
// Entry-2 total = g0/1e5 + aT ; entry-3 total = g0/0.2 + aT ; both end in sC.
__global__ void __launch_bounds__(256) k_chunk(const float* __restrict__ ucat,
                                               const float* __restrict__ uexp) {
    int gid = blockIdx.x * blockDim.x + threadIdx.x;   // 0 .. NCH*NCOL-1
    int col = gid & (NCOL - 1);
    int c   = gid >> 11;
    float A, B, C; get_thresholds(A, B, C);

    const float* pc = ucat + (size_t)c * CH * NCOL + col;
    const float* pe = uexp + (size_t)c * CH * NCOL + col;

    int   sA = 0, sB = 1, sC = 0;
    float aA = 0.f, aB = 0.f, aT = 0.f;
    float g0 = 0.f;

    #pragma unroll 5
    for (int k = 0; k < CH; k++) {
        float u1 = pc[(size_t)k * NCOL];
        float u2 = pe[(size_t)k * NCOL];
        float g  = -__logf(1.0f - u2);          // fast log ok: feeds offsets only
        int  f1  = f1_of(u1, A, B, C);

        if (k == 0) {
            g0 = g;                              // step-0 dwell noise for entry 2/3
        } else {
            aT = fmaf(g, invr_of(sC), aT);       // trajC current state at time k
            sC = advance(sC, f1);
        }
        aA = fmaf(g, invr_of(sA), aA);
        aB = fmaf(g, invr_of(sB), aB);
        sA = advance(sA, f1);
        sB = advance(sB, f1);
    }
    g_dA[gid] = aA;
    g_dB[gid] = aB;
    g_dC[gid] = fmaf(g0, c_invr[2], aT);
    g_dD[gid] = fmaf(g0, c_invr[3], aT);
    g_maps[gid] = (unsigned)sA | ((unsigned)sB << 8) | ((unsigned)sC << 16);
}

// ---------------- K2: per-column scan over chunks (entry states + offsets) ----------------
__global__ void __launch_bounds__(256) k_boundary() {
    int col = blockIdx.x * blockDim.x + threadIdx.x;   // 0..2047
    int s = 0;
    double t = 0.0;
    for (int c = 0; c < NCH; c++) {
        int idx = c * NCOL + col;
        g_entry[idx] = (unsigned char)s;
        g_offs[idx]  = (float)t;
        float dv = (s == 0) ? g_dA[idx]
                 : (s == 1) ? g_dB[idx]
                 : (s == 2) ? g_dC[idx]
                 :            g_dD[idx];
        t += (double)dv;
        unsigned m = g_maps[idx];
        int sh = (s < 2) ? s : 2;
        s = (int)((m >> (8 * sh)) & 3u);
    }
}

// searchsorted-left into bins[j] = (float)j * 0.002f, clamped to [0, NBINS]
__device__ __forceinline__ int bucketf(float t) {
    float jf = ceilf(t * 500.0f);
    int j = (int)jf;
    j = max(0, min(j, NBINS));
    while (j > 0      && (float)(j - 1) * 0.002f >= t) --j;
    while (j < NBINS  && (float)j       * 0.002f <  t) ++j;
    return j;
}

// ---------------- K3: final resolve: photons, cum_time, histogram ----------------
__global__ void __launch_bounds__(256) k_main(const float* __restrict__ ucat,
                                              const float* __restrict__ uexp,
                                              float* __restrict__ phot,
                                              float* __restrict__ cum) {
    int gid = blockIdx.x * blockDim.x + threadIdx.x;
    int col = gid & (NCOL - 1);
    int c   = gid >> 11;
    float A, B, C; get_thresholds(A, B, C);

    size_t base = (size_t)c * CH * NCOL + col;
    int   s = (int)g_entry[gid];
    float t = g_offs[gid];

    int run_bin = -1, run_cnt = 0, nz = 0;

    #pragma unroll 2
    for (int k = 0; k < CH; k++) {
        size_t idx = base + (size_t)k * NCOL;
        float u1 = ucat[idx];
        float u2 = uexp[idx];

        bool  ph = (s == 0);
        float g  = -log1pf(-u2);                 // accurate, matches reference
        float rate = (s == 0) ? c_rate[0] : ((s == 1) ? c_rate[1] : ((s == 2) ? c_rate[2] : c_rate[3]));
        float dwell = g / rate;                  // true IEEE div like reference
        t += dwell;

        phot[idx] = ph ? 1.0f : 0.0f;
        cum[idx]  = t;

        if (ph) {
            int b = bucketf(t);
            if (b == run_bin) {
                run_cnt++;
            } else {
                if (run_cnt) atomicAdd(&g_hist[run_bin], run_cnt);
                run_bin = b; run_cnt = 1;
            }
        } else {
            nz++;
        }

        int f1 = f1_of(u1, A, B, C);
        s = advance(s, f1);
    }
    if (run_cnt) atomicAdd(&g_hist[run_bin], run_cnt);

    // aggregate the heavily contended hist[0] (non-photon entries v==0) per warp
    int tot = __reduce_add_sync(0xffffffffu, nz);
    if ((threadIdx.x & 31) == 0 && tot) atomicAdd(&g_hist[0], tot);
}

// ---------------- K4: int hist -> float32 output tail ----------------
__global__ void k_hist_out(float* __restrict__ out_hist) {
    int i = blockIdx.x * blockDim.x + threadIdx.x;
    if (i < HISTN) out_hist[i] = (float)g_hist[i];
}

// ---------------- launch ----------------
extern "C" void kernel_launch(void* const* d_in, const int* in_sizes, int n_in,
                              void* d_out, int out_size) {
    const float* ucat = (const float*)d_in[0];
    const float* uexp = (const float*)d_in[1];
    float* out = (float*)d_out;

    const size_t n_elem = (size_t)STEPS * NCOL;   // 40,960,000
    float* out_phot = out;
    float* out_cum  = out + n_elem;
    float* out_hist = out + 2 * n_elem;

    const int th = 256;
    const int work_blocks = (NCH * NCOL) / th;    // 640
    const int hist_blocks = (HISTN + th - 1) / th;

    k_zero<<<hist_blocks, th>>>();
    k_chunk<<<work_blocks, th>>>(ucat, uexp);
    k_boundary<<<NCOL / th, th>>>();
    k_main<<<work_blocks, th>>>(ucat, uexp, out_phot, out_cum);
    k_hist_out<<<hist_blocks, th>>>(out_hist);
}